// round 15
// baseline (speedup 1.0000x reference)
#include <cuda_runtime.h>
#include <cuda_fp16.h>

// ---------------- problem constants ----------------
#define NMAX 100000
#define EMAX 1600000
#define INF 512
#define D1 64      // H1*F1 = 8*8
#define H1N 8
#define D2 40      // H2*F2 = 1*40

// ---------------- device scratch ----------------
__device__ __align__(16) __half g_h1h [NMAX * D1];   // fp16 layer1 features (gather payload)
__device__ __align__(16) __half g_el1h[NMAX * H1N];  // fp16 src-side attention
__device__ __align__(16) float  g_er1 [NMAX * H1N];  // fp32 dst-side attention
__device__ __align__(16) float  g_agg1[NMAX * D1];   // normalized layer1 output (pre-bias)
__device__ __align__(16) __half g_h2h [NMAX * D2];   // fp16 layer2 features
__device__ __align__(16) __half g_el2h[NMAX];
__device__ __align__(16) float  g_er2 [NMAX];
__device__ __align__(16) unsigned g_wf16[16 * 1152]; // W1 fp16, interleaved k-pair layout, per-tile
// CSR scratch (zeroed at module load; k_agg2 re-zeroes hist/counter each call)
__device__ int g_hist[NMAX];
__device__ int g_rowstart[NMAX];
__device__ int g_cursor[NMAX];
__device__ int g_sorted[EMAX];
__device__ int g_counter;

// ---------------- helpers ----------------
__device__ __forceinline__ float lrelu(float v) { return v >= 0.f ? v : 0.2f * v; }
__device__ __forceinline__ float eluf(float v)  { return v > 0.f ? v : expm1f(v); }

__device__ __forceinline__ void mma_f16(float* c,
                                        unsigned a0, unsigned a1, unsigned a2, unsigned a3,
                                        unsigned b0, unsigned b1) {
    asm volatile(
        "mma.sync.aligned.m16n8k16.row.col.f32.f16.f16.f32 "
        "{%0,%1,%2,%3},{%4,%5,%6,%7},{%8,%9},{%0,%1,%2,%3};"
        : "+f"(c[0]), "+f"(c[1]), "+f"(c[2]), "+f"(c[3])
        : "r"(a0), "r"(a1), "r"(a2), "r"(a3), "r"(b0), "r"(b1));
}
__device__ __forceinline__ void cpa16(unsigned sa, const void* g, int sz) {
    asm volatile("cp.async.ca.shared.global [%0], [%1], 16, %2;"
                 :: "r"(sa), "l"(g), "r"(sz));
}
__device__ __forceinline__ void cpa_commit() { asm volatile("cp.async.commit_group;"); }
__device__ __forceinline__ void cpa_wait2()  { asm volatile("cp.async.wait_group 2;"); }
__device__ __forceinline__ void cpa_wait0()  { asm volatile("cp.async.wait_group 0;"); }
__device__ __forceinline__ unsigned h2u(__half2 h) {
    unsigned u; asm("mov.b32 %0, %1;" : "=r"(u) : "r"(*(unsigned*)&h)); return u;
}

// ---------------- K_hist (g_hist arrives zeroed) ----------------
__global__ __launch_bounds__(256) void k_hist(const int* __restrict__ dst, int e) {
    int i = blockIdx.x * 256 + threadIdx.x;
    if (i < e) atomicAdd(&g_hist[dst[i]], 1);
}

// ---------------- K_rowalloc: warp-scanned row offsets ----------------
__global__ __launch_bounds__(256) void k_rowalloc(int n) {
    int d = blockIdx.x * 256 + threadIdx.x;
    int lane = threadIdx.x & 31;
    int c = (d < n) ? g_hist[d] : 0;
    int sum = c;
#pragma unroll
    for (int off = 1; off < 32; off <<= 1) {
        int v = __shfl_up_sync(0xffffffffu, sum, off);
        if (lane >= off) sum += v;
    }
    int total = __shfl_sync(0xffffffffu, sum, 31);
    int base = 0;
    if (lane == 31) base = atomicAdd(&g_counter, total);
    base = __shfl_sync(0xffffffffu, base, 31);
    if (d < n) {
        int st = base + sum - c;
        g_rowstart[d] = st;
        g_cursor[d]   = st;
    }
}

// ---------------- K_scatter ----------------
__global__ __launch_bounds__(256) void k_scatter(const int* __restrict__ src,
                                                 const int* __restrict__ dst, int e) {
    int i = blockIdx.x * 256 + threadIdx.x;
    if (i >= e) return;
    int p = atomicAdd(&g_cursor[dst[i]], 1);
    g_sorted[p] = src[i];
}

// ---------------- K_wconv: W1 fp32 -> fp16 interleaved k-pair layout (per 32-k tile) ----------------
// word(tile, kp_local, n) = tile*1152 + kp_local*72 + n ; low half = even k, high = odd k.
__global__ __launch_bounds__(256) void k_wconv(const float* __restrict__ W1) {
    int idx = blockIdx.x * 256 + threadIdx.x;        // 0..16383
    int kp = idx >> 6;                               // global k-pair 0..255
    int nn = idx & 63;
    int tile = kp >> 4, kpl = kp & 15;
    float lo = W1[(size_t)(2 * kp) * D1 + nn];
    float hi = W1[(size_t)(2 * kp + 1) * D1 + nn];
    g_wf16[tile * 1152 + kpl * 72 + nn] = h2u(__floats2half2_rn(lo, hi));
}

// ---------------- K1: h1 = x @ W1, fp16 mma, 3-stage cp.async ring for x AND W ----------------
// Dynamic smem (floats): xs 3 stages x [128][36] fp32 (0..13823),
//                        ws 3 stages x 1152 words (13824..17279), al/ar (17280..17407).
// Epilogue ds[128][64] fp32 overlays xs stages 0-1.
__global__ __launch_bounds__(256) void k_gemm1(const float* __restrict__ x,
                                               const float* __restrict__ al1,
                                               const float* __restrict__ ar1, int n) {
    extern __shared__ __align__(16) float smd[];
    unsigned* ws = (unsigned*)(smd + 13824);
    float* alr = smd + 17280;

    const int tx = threadIdx.x;
    const int row0 = blockIdx.x * 128;
    const int warp = tx >> 5;
    const int lane = tx & 31;
    const int g  = lane >> 2;
    const int tg = lane & 3;
    const int wrow = warp * 16;

    const unsigned smem_base = (unsigned)__cvta_generic_to_shared(smd);

    if (tx < 64) alr[tx] = al1[tx];
    else if (tx < 128) alr[tx] = ar1[tx - 64];

    // per-thread x-chunk coordinates (4 chunks of 16B per tile)
    int crow[4], ccol[4];
#pragma unroll
    for (int it = 0; it < 4; it++) {
        int slot = tx + it * 256;
        crow[it] = slot >> 3;
        ccol[it] = slot & 7;
    }

    // issue one tile's copies (x + W) into stage tt%3
    auto issue_tile = [&](int tt) {
        int stage = tt % 3;
        unsigned xsb = smem_base + (unsigned)(stage * 4608 * 4);
#pragma unroll
        for (int it = 0; it < 4; it++) {
            int grow = row0 + crow[it];
            unsigned sa = xsb + (unsigned)((crow[it] * 36 + ccol[it] * 4) * 4);
            cpa16(sa, x + (size_t)grow * INF + tt * 32 + ccol[it] * 4, grow < n ? 16 : 0);
        }
        unsigned wsb = smem_base + (unsigned)((13824 + stage * 1152) * 4);
        cpa16(wsb + tx * 16, g_wf16 + tt * 1152 + tx * 4, 16);
        if (tx < 32)
            cpa16(wsb + (256 + tx) * 16, g_wf16 + tt * 1152 + (256 + tx) * 4, 16);
        cpa_commit();
    };

    issue_tile(0); issue_tile(1); issue_tile(2);

    float acc[8][4];
#pragma unroll
    for (int j = 0; j < 8; j++)
#pragma unroll
        for (int q = 0; q < 4; q++) acc[j][q] = 0.f;

    for (int tt = 0; tt < 16; tt++) {
        if (tt <= 12) cpa_wait2(); else cpa_wait0();
        __syncthreads();

        const float* xc = smd + (tt % 3) * 4608;
        const unsigned* wc = ws + (tt % 3) * 1152;
#pragma unroll
        for (int ks = 0; ks < 2; ks++) {
            int base = (wrow + g) * 36 + ks * 16 + 2 * tg;
            float2 fa0 = *(const float2*)(xc + base);
            float2 fa1 = *(const float2*)(xc + base + 8 * 36);
            float2 fa2 = *(const float2*)(xc + base + 8);
            float2 fa3 = *(const float2*)(xc + base + 8 * 36 + 8);
            unsigned a0 = h2u(__floats2half2_rn(fa0.x, fa0.y));
            unsigned a1 = h2u(__floats2half2_rn(fa1.x, fa1.y));
            unsigned a2 = h2u(__floats2half2_rn(fa2.x, fa2.y));
            unsigned a3 = h2u(__floats2half2_rn(fa3.x, fa3.y));
            const unsigned* bp0 = wc + (ks * 8 + tg) * 72 + g;
            const unsigned* bp1 = bp0 + 4 * 72;
#pragma unroll
            for (int j = 0; j < 8; j++)
                mma_f16(acc[j], a0, a1, a2, a3, bp0[8 * j], bp1[8 * j]);
        }
        __syncthreads();
        if (tt + 3 < 16) issue_tile(tt + 3);
    }

    // ---- epilogue: accumulators -> smem ds[128][64] fp32 (overlays xs) ----
    float* ds = smd;
#pragma unroll
    for (int j = 0; j < 8; j++) {
        *(float2*)&ds[(wrow + g) * 64 + 8 * j + 2 * tg]     = make_float2(acc[j][0], acc[j][1]);
        *(float2*)&ds[(wrow + g + 8) * 64 + 8 * j + 2 * tg] = make_float2(acc[j][2], acc[j][3]);
    }
    __syncthreads();

    {
        int row = tx >> 1;
        int ch = tx & 1;
        int grow = row0 + row;
        if (grow < n) {
            const float* dp  = ds + row * 64 + ch * 32;
            const float* alp = alr + ch * 32;
            const float* arp = alr + 64 + ch * 32;
            float h[32];
#pragma unroll
            for (int q = 0; q < 8; q++) *(float4*)&h[q * 4] = *(const float4*)(dp + q * 4);

            float elv[4], erv[4];
#pragma unroll
            for (int q = 0; q < 4; q++) {
                float el = 0.f, er = 0.f;
#pragma unroll
                for (int c = 0; c < 8; c++) {
                    el = fmaf(h[q * 8 + c], alp[q * 8 + c], el);
                    er = fmaf(h[q * 8 + c], arp[q * 8 + c], er);
                }
                elv[q] = el; erv[q] = er;
            }
            __half2 ph[16];
#pragma unroll
            for (int q = 0; q < 16; q++) ph[q] = __floats2half2_rn(h[2 * q], h[2 * q + 1]);
            uint4* hop = (uint4*)(g_h1h + (size_t)grow * D1 + ch * 32);
#pragma unroll
            for (int q = 0; q < 4; q++) hop[q] = ((uint4*)ph)[q];

            __half e4[4];
#pragma unroll
            for (int q = 0; q < 4; q++) e4[q] = __float2half(elv[q]);
            *(uint2*)(g_el1h + (size_t)grow * 8 + ch * 4) = *(uint2*)e4;
            *(float4*)(g_er1 + (size_t)grow * 8 + ch * 4) =
                make_float4(erv[0], erv[1], erv[2], erv[3]);
        }
    }
}

// ---------------- K3: layer1 CSR aggregation, batched ids + shuffle (warp per dst) ----------------
__global__ __launch_bounds__(256) void k_agg1(int n) {
    int d = blockIdx.x * 8 + (threadIdx.x >> 5);
    if (d >= n) return;
    int lane = threadIdx.x & 31;
    int j = lane & 7;        // slot / head 0..7
    int g = lane >> 3;       // edge group 0..3

    float er = g_er1[(size_t)d * 8 + j];
    int k0 = g_rowstart[d];
    int deg = g_cursor[d] - k0;

    float acc[8] = {0.f, 0.f, 0.f, 0.f, 0.f, 0.f, 0.f, 0.f};
    float denom = 0.f;
    for (int base = 0; base < deg; base += 32) {
        int cnt = deg - base; if (cnt > 32) cnt = 32;
        int myid = 0;
        if (lane < cnt) myid = __ldg(g_sorted + k0 + base + lane);
        int trips = (cnt + 3) >> 2;
        for (int t = 0; t < trips; t++) {
            int i = t * 4 + g;                          // i <= 31 always
            int s = __shfl_sync(0xffffffffu, myid, i);
            if (i < cnt) {
                float el = __half2float(__ldg(g_el1h + (size_t)s * 8 + j));
                uint4 hv = __ldg((const uint4*)(g_h1h + (size_t)s * D1 + j * 8));
                float ex = __expf(lrelu(el + er));
                const __half2* hp = (const __half2*)&hv;
#pragma unroll
                for (int q = 0; q < 4; q++) {
                    float2 f = __half22float2(hp[q]);
                    acc[2*q]   = fmaf(ex, f.x, acc[2*q]);
                    acc[2*q+1] = fmaf(ex, f.y, acc[2*q+1]);
                }
                denom += ex;
            }
        }
    }
    __syncwarp();
#pragma unroll
    for (int q = 0; q < 8; q++) {
        acc[q] += __shfl_down_sync(0xffffffffu, acc[q], 16);
        acc[q] += __shfl_down_sync(0xffffffffu, acc[q], 8);
    }
    denom += __shfl_down_sync(0xffffffffu, denom, 16);
    denom += __shfl_down_sync(0xffffffffu, denom, 8);

    if (g == 0) {
        float iv = denom > 0.f ? __fdividef(1.f, denom) : 0.f;
        float* op = g_agg1 + (size_t)d * D1 + j * 8;
        *(float4*)(op)     = make_float4(acc[0]*iv, acc[1]*iv, acc[2]*iv, acc[3]*iv);
        *(float4*)(op + 4) = make_float4(acc[4]*iv, acc[5]*iv, acc[6]*iv, acc[7]*iv);
    }
}

// ---------------- K4: node: ELU(agg1 + b1), GEMM2 (64->40) vectorized, el2/er2, fp16 h2 ----------------
__global__ __launch_bounds__(256) void k_node2(const float* __restrict__ W2,
                                               const float* __restrict__ al2,
                                               const float* __restrict__ ar2,
                                               const float* __restrict__ b1, int n) {
    __shared__ __align__(16) float w2s[64 * 40];
    __shared__ float sal[40], sar[40], sb1[64];
    for (int i = threadIdx.x; i < 64 * 40; i += 256) w2s[i] = W2[i];
    if (threadIdx.x < 40) { sal[threadIdx.x] = al2[threadIdx.x]; sar[threadIdx.x] = ar2[threadIdx.x]; }
    if (threadIdx.x < 64) sb1[threadIdx.x] = b1[threadIdx.x];
    __syncthreads();
    int nid = blockIdx.x * 256 + threadIdx.x;
    if (nid >= n) return;

    float acc[40];
#pragma unroll
    for (int c = 0; c < 40; c++) acc[c] = 0.f;

    const float4* ap = (const float4*)(g_agg1 + (size_t)nid * D1);
    for (int j = 0; j < 16; j++) {
        float4 tv = ap[j];
        const float* bp = sb1 + j * 4;
        float v0 = eluf(tv.x + bp[0]);
        float v1 = eluf(tv.y + bp[1]);
        float v2 = eluf(tv.z + bp[2]);
        float v3 = eluf(tv.w + bp[3]);
        const float4* w0 = (const float4*)&w2s[(j * 4 + 0) * 40];
        const float4* w1 = (const float4*)&w2s[(j * 4 + 1) * 40];
        const float4* w2 = (const float4*)&w2s[(j * 4 + 2) * 40];
        const float4* w3 = (const float4*)&w2s[(j * 4 + 3) * 40];
#pragma unroll
        for (int q = 0; q < 10; q++) {
            float4 a = w0[q], b = w1[q], c = w2[q], d = w3[q];
            acc[q*4+0] = fmaf(v0, a.x, fmaf(v1, b.x, fmaf(v2, c.x, fmaf(v3, d.x, acc[q*4+0]))));
            acc[q*4+1] = fmaf(v0, a.y, fmaf(v1, b.y, fmaf(v2, c.y, fmaf(v3, d.y, acc[q*4+1]))));
            acc[q*4+2] = fmaf(v0, a.z, fmaf(v1, b.z, fmaf(v2, c.z, fmaf(v3, d.z, acc[q*4+2]))));
            acc[q*4+3] = fmaf(v0, a.w, fmaf(v1, b.w, fmaf(v2, c.w, fmaf(v3, d.w, acc[q*4+3]))));
        }
    }

    float ela = 0.f, era = 0.f;
#pragma unroll
    for (int c = 0; c < 40; c++) {
        ela = fmaf(acc[c], sal[c], ela);
        era = fmaf(acc[c], sar[c], era);
    }
    __half2 hp[20];
#pragma unroll
    for (int q = 0; q < 20; q++) hp[q] = __floats2half2_rn(acc[2*q], acc[2*q+1]);
    uint4* op = (uint4*)(g_h2h + (size_t)nid * D2);
#pragma unroll
    for (int q = 0; q < 5; q++) op[q] = ((uint4*)hp)[q];
    g_el2h[nid] = __float2half(ela);
    g_er2 [nid] = era;
}

// ---------------- K5: layer2 CSR agg + fused bias + log_softmax, batched ids ----------------
__global__ __launch_bounds__(256) void k_agg2(const float* __restrict__ b2,
                                              float* __restrict__ out, int n) {
    int d = blockIdx.x * 8 + (threadIdx.x >> 5);
    int lane = threadIdx.x & 31;

    if (lane == 0 && d < n) g_hist[d] = 0;
    if (d == 0 && lane == 0) g_counter = 0;

    if (d >= n) return;
    int j = lane % 10;
    int g = lane / 10;       // 0,1,2 active; lanes 30,31 (g==3) join shuffles only

    float er = g_er2[d];
    int k0 = g_rowstart[d];
    int deg = g_cursor[d] - k0;

    float acc[4] = {0.f, 0.f, 0.f, 0.f};
    float denom = 0.f;
    for (int base = 0; base < deg; base += 32) {
        int cnt = deg - base; if (cnt > 32) cnt = 32;
        int myid = 0;
        if (lane < cnt) myid = __ldg(g_sorted + k0 + base + lane);
        int trips = (cnt + 2) / 3;
        for (int t = 0; t < trips; t++) {
            int i = t * 3 + g;
            int s = __shfl_sync(0xffffffffu, myid, i & 31);
            if (g < 3 && i < cnt) {
                float el = __half2float(__ldg(g_el2h + s));
                uint2 hv = __ldg((const uint2*)(g_h2h + (size_t)s * D2 + j * 4));
                float ex = __expf(lrelu(el + er));
                const __half2* hp = (const __half2*)&hv;
                float2 f0 = __half22float2(hp[0]);
                float2 f1 = __half22float2(hp[1]);
                acc[0] = fmaf(ex, f0.x, acc[0]);
                acc[1] = fmaf(ex, f0.y, acc[1]);
                acc[2] = fmaf(ex, f1.x, acc[2]);
                acc[3] = fmaf(ex, f1.y, acc[3]);
                denom += ex;
            }
        }
    }
    __syncwarp();
#pragma unroll
    for (int q = 0; q < 4; q++) {
        float a = __shfl_down_sync(0xffffffffu, acc[q], 10);
        float b = __shfl_down_sync(0xffffffffu, acc[q], 20);
        acc[q] += a + b;
    }
    {
        float a = __shfl_down_sync(0xffffffffu, denom, 10);
        float b = __shfl_down_sync(0xffffffffu, denom, 20);
        denom += a + b;
    }

    float v[4];
    float m = -1e30f;
    float iv = denom > 0.f ? __fdividef(1.f, denom) : 0.f;
    if (lane < 10) {
#pragma unroll
        for (int q = 0; q < 4; q++) {
            v[q] = acc[q] * iv + __ldg(b2 + j * 4 + q);
            m = fmaxf(m, v[q]);
        }
    }
#pragma unroll
    for (int off = 1; off < 16; off <<= 1)
        m = fmaxf(m, __shfl_xor_sync(0xffffffffu, m, off));
    float s = 0.f;
    if (lane < 10) {
#pragma unroll
        for (int q = 0; q < 4; q++) s += __expf(v[q] - m);
    }
#pragma unroll
    for (int off = 1; off < 16; off <<= 1)
        s += __shfl_xor_sync(0xffffffffu, s, off);

    if (lane < 10) {
        float lse = m + logf(s);
        *(float4*)(out + (size_t)d * D2 + j * 4) =
            make_float4(v[0] - lse, v[1] - lse, v[2] - lse, v[3] - lse);
    }
}

// ---------------- launch ----------------
extern "C" void kernel_launch(void* const* d_in, const int* in_sizes, int n_in,
                              void* d_out, int out_size) {
    const float* x   = (const float*)d_in[0];
    const int*   src = (const int*)d_in[1];
    const int*   dst = (const int*)d_in[2];
    const float* W1  = (const float*)d_in[3];
    const float* al1 = (const float*)d_in[4];
    const float* ar1 = (const float*)d_in[5];
    const float* b1  = (const float*)d_in[6];
    const float* W2  = (const float*)d_in[7];
    const float* al2 = (const float*)d_in[8];
    const float* ar2 = (const float*)d_in[9];
    const float* b2  = (const float*)d_in[10];

    int n = in_sizes[0] / INF;
    int e = in_sizes[1];

    const int GEMM_SMEM = 17408 * 4;   // 69,632 B dynamic smem

    int nb_node = (n + 255) / 256;
    int nb_edge = (e + 255) / 256;
    int nb_gemm = (n + 127) / 128;
    int nb_warp = (n + 7) / 8;

    static cudaStream_t s_side = nullptr;
    static cudaEvent_t  s_evA  = nullptr;
    static cudaEvent_t  s_evB  = nullptr;
    if (s_side == nullptr) {
        cudaStreamCreateWithFlags(&s_side, cudaStreamNonBlocking);
        cudaEventCreateWithFlags(&s_evA, cudaEventDisableTiming);
        cudaEventCreateWithFlags(&s_evB, cudaEventDisableTiming);
        cudaFuncSetAttribute(k_gemm1, cudaFuncAttributeMaxDynamicSharedMemorySize, GEMM_SMEM);
    }

    // fork: CSR build on side stream; W-convert + GEMM1 on main stream
    cudaEventRecord(s_evA, 0);
    cudaStreamWaitEvent(s_side, s_evA, 0);

    k_hist    <<<nb_edge, 256, 0, s_side>>>(dst, e);       // 1
    k_rowalloc<<<nb_node, 256, 0, s_side>>>(n);            // 2
    k_wconv   <<<64, 256>>>(W1);                           // 3 (main)
    k_gemm1   <<<nb_gemm, 256, GEMM_SMEM>>>(x, al1, ar1, n); // 4 (main) -> ncu profiles this
    k_scatter <<<nb_edge, 256, 0, s_side>>>(src, dst, e);  // 5 (side)
    cudaEventRecord(s_evB, s_side);

    // join
    cudaStreamWaitEvent(0, s_evB, 0);

    k_agg1    <<<nb_warp, 256>>>(n);
    k_node2   <<<nb_node, 256>>>(W2, al2, ar2, b1, n);
    k_agg2    <<<nb_warp, 256>>>(b2, (float*)d_out, n);
}

// round 16
// speedup vs baseline: 1.2062x; 1.2062x over previous
#include <cuda_runtime.h>
#include <cuda_fp16.h>

// ---------------- problem constants ----------------
#define NMAX 100000
#define EMAX 1600000
#define INF 512
#define D1 64      // H1*F1 = 8*8
#define H1N 8
#define D2 40      // H2*F2 = 1*40

// ---------------- device scratch ----------------
__device__ __align__(16) __half g_h1h [NMAX * D1];   // fp16 layer1 features (gather payload)
__device__ __align__(16) __half g_el1h[NMAX * H1N];  // fp16 src-side attention
__device__ __align__(16) float  g_er1 [NMAX * H1N];  // fp32 dst-side attention
__device__ __align__(16) float  g_agg1[NMAX * D1];   // normalized layer1 output (pre-bias)
__device__ __align__(16) __half g_h2h [NMAX * D2];   // fp16 layer2 features
__device__ __align__(16) __half g_el2h[NMAX];
__device__ __align__(16) float  g_er2 [NMAX];
// CSR scratch (zeroed at module load; k_agg2 re-zeroes hist/counter each call)
__device__ int g_hist[NMAX];
__device__ int g_rowstart[NMAX];
__device__ int g_cursor[NMAX];
__device__ int g_sorted[EMAX];
__device__ int g_counter;

// ---------------- helpers ----------------
__device__ __forceinline__ float lrelu(float v) { return v >= 0.f ? v : 0.2f * v; }
__device__ __forceinline__ float eluf(float v)  { return v > 0.f ? v : expm1f(v); }

__device__ __forceinline__ void mma_f16(float* c,
                                        unsigned a0, unsigned a1, unsigned a2, unsigned a3,
                                        unsigned b0, unsigned b1) {
    asm volatile(
        "mma.sync.aligned.m16n8k16.row.col.f32.f16.f16.f32 "
        "{%0,%1,%2,%3},{%4,%5,%6,%7},{%8,%9},{%0,%1,%2,%3};"
        : "+f"(c[0]), "+f"(c[1]), "+f"(c[2]), "+f"(c[3])
        : "r"(a0), "r"(a1), "r"(a2), "r"(a3), "r"(b0), "r"(b1));
}
// L2-only (bypass L1) 16B async copy — streaming data with zero reuse.
__device__ __forceinline__ void cpa16cg(unsigned sa, const void* g, int sz) {
    asm volatile("cp.async.cg.shared.global [%0], [%1], 16, %2;"
                 :: "r"(sa), "l"(g), "r"(sz));
}
__device__ __forceinline__ void cpa_commit() {
    asm volatile("cp.async.commit_group;");
}
__device__ __forceinline__ void cpa_wait0() {
    asm volatile("cp.async.wait_group 0;");
}
__device__ __forceinline__ unsigned h2u(__half2 h) {
    unsigned u; asm("mov.b32 %0, %1;" : "=r"(u) : "r"(*(unsigned*)&h)); return u;
}

// ---------------- K_hist (g_hist arrives zeroed) ----------------
__global__ __launch_bounds__(256) void k_hist(const int* __restrict__ dst, int e) {
    int i = blockIdx.x * 256 + threadIdx.x;
    if (i < e) atomicAdd(&g_hist[dst[i]], 1);
}

// ---------------- K_rowalloc: warp-scanned row offsets ----------------
__global__ __launch_bounds__(256) void k_rowalloc(int n) {
    int d = blockIdx.x * 256 + threadIdx.x;
    int lane = threadIdx.x & 31;
    int c = (d < n) ? g_hist[d] : 0;
    int sum = c;
#pragma unroll
    for (int off = 1; off < 32; off <<= 1) {
        int v = __shfl_up_sync(0xffffffffu, sum, off);
        if (lane >= off) sum += v;
    }
    int total = __shfl_sync(0xffffffffu, sum, 31);
    int base = 0;
    if (lane == 31) base = atomicAdd(&g_counter, total);
    base = __shfl_sync(0xffffffffu, base, 31);
    if (d < n) {
        int st = base + sum - c;
        g_rowstart[d] = st;
        g_cursor[d]   = st;
    }
}

// ---------------- K_scatter ----------------
__global__ __launch_bounds__(256) void k_scatter(const int* __restrict__ src,
                                                 const int* __restrict__ dst, int e) {
    int i = blockIdx.x * 256 + threadIdx.x;
    if (i >= e) return;
    int p = atomicAdd(&g_cursor[dst[i]], 1);
    g_sorted[p] = src[i];
}

// ---------------- K1: h1 = x @ W1, fp16 mma m16n8k16, cp.async.cg double-buffered x ----------------
// smem (floats): xs 2 stages x [128][36] fp32 (0..9216), ws fp16 2 stages x 2304h (9216..11520),
// al/ar at 11520..11648.  Epilogue ds[128][64] fp32 overlays xs (0..8192).
__global__ __launch_bounds__(256) void k_gemm1(const float* __restrict__ x,
                                               const float* __restrict__ W1,
                                               const float* __restrict__ al1,
                                               const float* __restrict__ ar1, int n) {
    __shared__ __align__(16) float sm[11648];
    __half* ws_h = (__half*)(sm + 9216);
    unsigned* ws_u = (unsigned*)ws_h;

    const int tx = threadIdx.x;
    const int row0 = blockIdx.x * 128;
    const int warp = tx >> 5;
    const int lane = tx & 31;
    const int g  = lane >> 2;
    const int tg = lane & 3;
    const int wrow = warp * 16;

    const unsigned xs_base = (unsigned)__cvta_generic_to_shared(sm);

    if (tx < 64) sm[11520 + tx] = al1[tx];
    else if (tx < 128) sm[11520 + tx] = ar1[tx - 64];

    // per-thread x-chunk coordinates (4 chunks of 16B per tile)
    int crow[4], ccol[4];
#pragma unroll
    for (int it = 0; it < 4; it++) {
        int slot = tx + it * 256;
        crow[it] = slot >> 3;        // row 0..127
        ccol[it] = slot & 7;         // 16B chunk 0..7 within 32-float row
    }

    float4 wr[2];

    // ---- prologue: issue x tile 0, load+store W tile 0 ----
#pragma unroll
    for (int it = 0; it < 4; it++) {
        int grow = row0 + crow[it];
        unsigned sa = xs_base + (unsigned)((crow[it] * 36 + ccol[it] * 4) * 4);
        cpa16cg(sa, x + (size_t)grow * INF + ccol[it] * 4, grow < n ? 16 : 0);
    }
    cpa_commit();
#pragma unroll
    for (int it = 0; it < 2; it++) {
        int slot = tx + it * 256;
        int k = slot >> 4;
        int n4 = (slot & 15) << 2;
        wr[it] = *(const float4*)(W1 + (size_t)k * D1 + n4);
    }
#pragma unroll
    for (int it = 0; it < 2; it++) {
        int slot = tx + it * 256;
        int k = slot >> 4;
        int n4 = (slot & 15) << 2;
        int base = (k >> 1) * 144 + (k & 1);
        ws_h[base + (n4 + 0) * 2] = __float2half(wr[it].x);
        ws_h[base + (n4 + 1) * 2] = __float2half(wr[it].y);
        ws_h[base + (n4 + 2) * 2] = __float2half(wr[it].z);
        ws_h[base + (n4 + 3) * 2] = __float2half(wr[it].w);
    }
    cpa_wait0();
    __syncthreads();

    float acc[8][4];
#pragma unroll
    for (int j = 0; j < 8; j++)
#pragma unroll
        for (int q = 0; q < 4; q++) acc[j][q] = 0.f;

    for (int tt = 0; tt < 16; tt++) {
        const int cur = tt & 1;
        // issue async copies + W loads for tile tt+1 (in flight during compute)
        if (tt < 15) {
            int k0 = (tt + 1) * 32;
            int nxt = (tt + 1) & 1;
#pragma unroll
            for (int it = 0; it < 4; it++) {
                int grow = row0 + crow[it];
                unsigned sa = xs_base + (unsigned)((nxt * 4608 + crow[it] * 36 + ccol[it] * 4) * 4);
                cpa16cg(sa, x + (size_t)grow * INF + k0 + ccol[it] * 4, grow < n ? 16 : 0);
            }
            cpa_commit();
#pragma unroll
            for (int it = 0; it < 2; it++) {
                int slot = tx + it * 256;
                int k = slot >> 4;
                int n4 = (slot & 15) << 2;
                wr[it] = *(const float4*)(W1 + (size_t)(k0 + k) * D1 + n4);
            }
        }

        // compute tile tt: 2 k16 steps, A frags from fp32 smem (cvt at load)
        const float* xc = sm + cur * 4608;
#pragma unroll
        for (int ks = 0; ks < 2; ks++) {
            int base = (wrow + g) * 36 + ks * 16 + 2 * tg;
            float2 fa0 = *(const float2*)(xc + base);
            float2 fa1 = *(const float2*)(xc + base + 8 * 36);
            float2 fa2 = *(const float2*)(xc + base + 8);
            float2 fa3 = *(const float2*)(xc + base + 8 * 36 + 8);
            unsigned a0 = h2u(__floats2half2_rn(fa0.x, fa0.y));
            unsigned a1 = h2u(__floats2half2_rn(fa1.x, fa1.y));
            unsigned a2 = h2u(__floats2half2_rn(fa2.x, fa2.y));
            unsigned a3 = h2u(__floats2half2_rn(fa3.x, fa3.y));
            const unsigned* bp0 = ws_u + cur * 1152 + (ks * 8 + tg) * 72 + g;
            const unsigned* bp1 = bp0 + 4 * 72;
#pragma unroll
            for (int j = 0; j < 8; j++)
                mma_f16(acc[j], a0, a1, a2, a3, bp0[8 * j], bp1[8 * j]);
        }

        if (tt < 15) {
            int nxt = (tt + 1) & 1;
#pragma unroll
            for (int it = 0; it < 2; it++) {
                int slot = tx + it * 256;
                int k = slot >> 4;
                int n4 = (slot & 15) << 2;
                int base = nxt * 2304 + (k >> 1) * 144 + (k & 1);
                ws_h[base + (n4 + 0) * 2] = __float2half(wr[it].x);
                ws_h[base + (n4 + 1) * 2] = __float2half(wr[it].y);
                ws_h[base + (n4 + 2) * 2] = __float2half(wr[it].z);
                ws_h[base + (n4 + 3) * 2] = __float2half(wr[it].w);
            }
            cpa_wait0();
            __syncthreads();
        }
    }
    __syncthreads();   // all warps done reading xs before ds overlay

    // ---- epilogue: accumulators -> smem ds[128][64] fp32 ----
    float* ds = sm;
#pragma unroll
    for (int j = 0; j < 8; j++) {
        *(float2*)&ds[(wrow + g) * 64 + 8 * j + 2 * tg]     = make_float2(acc[j][0], acc[j][1]);
        *(float2*)&ds[(wrow + g + 8) * 64 + 8 * j + 2 * tg] = make_float2(acc[j][2], acc[j][3]);
    }
    __syncthreads();

    // thread tx: row = tx>>1, half ch = tx&1 -> cols ch*32..+31 (heads 4ch..4ch+3)
    {
        int row = tx >> 1;
        int ch = tx & 1;
        int grow = row0 + row;
        if (grow < n) {
            const float* dp  = ds + row * 64 + ch * 32;
            const float* alp = sm + 11520 + ch * 32;
            const float* arp = sm + 11584 + ch * 32;
            float h[32];
#pragma unroll
            for (int q = 0; q < 8; q++) *(float4*)&h[q * 4] = *(const float4*)(dp + q * 4);

            float elv[4], erv[4];
#pragma unroll
            for (int q = 0; q < 4; q++) {
                float el = 0.f, er = 0.f;
#pragma unroll
                for (int c = 0; c < 8; c++) {
                    el = fmaf(h[q * 8 + c], alp[q * 8 + c], el);
                    er = fmaf(h[q * 8 + c], arp[q * 8 + c], er);
                }
                elv[q] = el; erv[q] = er;
            }
            __half2 ph[16];
#pragma unroll
            for (int q = 0; q < 16; q++) ph[q] = __floats2half2_rn(h[2 * q], h[2 * q + 1]);
            uint4* hop = (uint4*)(g_h1h + (size_t)grow * D1 + ch * 32);
#pragma unroll
            for (int q = 0; q < 4; q++) hop[q] = ((uint4*)ph)[q];

            __half e4[4];
#pragma unroll
            for (int q = 0; q < 4; q++) e4[q] = __float2half(elv[q]);
            *(uint2*)(g_el1h + (size_t)grow * 8 + ch * 4) = *(uint2*)e4;
            *(float4*)(g_er1 + (size_t)grow * 8 + ch * 4) =
                make_float4(erv[0], erv[1], erv[2], erv[3]);
        }
    }
}

// ---------------- K3: layer1 CSR aggregation (warp per dst, 8 slots x 4 edge groups) ----------------
__global__ __launch_bounds__(256) void k_agg1(int n) {
    int d = blockIdx.x * 8 + (threadIdx.x >> 5);
    if (d >= n) return;
    int lane = threadIdx.x & 31;
    int j = lane & 7;        // slot / head 0..7
    int g = lane >> 3;       // edge group 0..3

    float er = g_er1[(size_t)d * 8 + j];
    int k0 = g_rowstart[d], k1 = g_cursor[d];

    float acc[8] = {0.f, 0.f, 0.f, 0.f, 0.f, 0.f, 0.f, 0.f};
    float denom = 0.f;
    for (int k = k0 + g; k < k1; k += 4) {
        int s = __ldg(g_sorted + k);
        float el = __half2float(__ldg(g_el1h + (size_t)s * 8 + j));
        uint4 hv = __ldg((const uint4*)(g_h1h + (size_t)s * D1 + j * 8));
        float ex = __expf(lrelu(el + er));
        const __half2* hp = (const __half2*)&hv;
#pragma unroll
        for (int q = 0; q < 4; q++) {
            float2 f = __half22float2(hp[q]);
            acc[2*q]   = fmaf(ex, f.x, acc[2*q]);
            acc[2*q+1] = fmaf(ex, f.y, acc[2*q+1]);
        }
        denom += ex;
    }
    __syncwarp();
#pragma unroll
    for (int q = 0; q < 8; q++) {
        acc[q] += __shfl_down_sync(0xffffffffu, acc[q], 16);
        acc[q] += __shfl_down_sync(0xffffffffu, acc[q], 8);
    }
    denom += __shfl_down_sync(0xffffffffu, denom, 16);
    denom += __shfl_down_sync(0xffffffffu, denom, 8);

    if (g == 0) {
        float iv = denom > 0.f ? __fdividef(1.f, denom) : 0.f;
        float* op = g_agg1 + (size_t)d * D1 + j * 8;
        *(float4*)(op)     = make_float4(acc[0]*iv, acc[1]*iv, acc[2]*iv, acc[3]*iv);
        *(float4*)(op + 4) = make_float4(acc[4]*iv, acc[5]*iv, acc[6]*iv, acc[7]*iv);
    }
}

// ---------------- K4: node: ELU(agg1 + b1), GEMM2 (64->40) vectorized, el2/er2, fp16 h2 ----------------
__global__ __launch_bounds__(256) void k_node2(const float* __restrict__ W2,
                                               const float* __restrict__ al2,
                                               const float* __restrict__ ar2,
                                               const float* __restrict__ b1, int n) {
    __shared__ __align__(16) float w2s[64 * 40];
    __shared__ float sal[40], sar[40], sb1[64];
    for (int i = threadIdx.x; i < 64 * 40; i += 256) w2s[i] = W2[i];
    if (threadIdx.x < 40) { sal[threadIdx.x] = al2[threadIdx.x]; sar[threadIdx.x] = ar2[threadIdx.x]; }
    if (threadIdx.x < 64) sb1[threadIdx.x] = b1[threadIdx.x];
    __syncthreads();
    int nid = blockIdx.x * 256 + threadIdx.x;
    if (nid >= n) return;

    float acc[40];
#pragma unroll
    for (int c = 0; c < 40; c++) acc[c] = 0.f;

    const float4* ap = (const float4*)(g_agg1 + (size_t)nid * D1);
    for (int j = 0; j < 16; j++) {
        float4 tv = ap[j];
        const float* bp = sb1 + j * 4;
        float v0 = eluf(tv.x + bp[0]);
        float v1 = eluf(tv.y + bp[1]);
        float v2 = eluf(tv.z + bp[2]);
        float v3 = eluf(tv.w + bp[3]);
        const float4* w0 = (const float4*)&w2s[(j * 4 + 0) * 40];
        const float4* w1 = (const float4*)&w2s[(j * 4 + 1) * 40];
        const float4* w2 = (const float4*)&w2s[(j * 4 + 2) * 40];
        const float4* w3 = (const float4*)&w2s[(j * 4 + 3) * 40];
#pragma unroll
        for (int q = 0; q < 10; q++) {
            float4 a = w0[q], b = w1[q], c = w2[q], d = w3[q];
            acc[q*4+0] = fmaf(v0, a.x, fmaf(v1, b.x, fmaf(v2, c.x, fmaf(v3, d.x, acc[q*4+0]))));
            acc[q*4+1] = fmaf(v0, a.y, fmaf(v1, b.y, fmaf(v2, c.y, fmaf(v3, d.y, acc[q*4+1]))));
            acc[q*4+2] = fmaf(v0, a.z, fmaf(v1, b.z, fmaf(v2, c.z, fmaf(v3, d.z, acc[q*4+2]))));
            acc[q*4+3] = fmaf(v0, a.w, fmaf(v1, b.w, fmaf(v2, c.w, fmaf(v3, d.w, acc[q*4+3]))));
        }
    }

    float ela = 0.f, era = 0.f;
#pragma unroll
    for (int c = 0; c < 40; c++) {
        ela = fmaf(acc[c], sal[c], ela);
        era = fmaf(acc[c], sar[c], era);
    }
    __half2 hp[20];
#pragma unroll
    for (int q = 0; q < 20; q++) hp[q] = __floats2half2_rn(acc[2*q], acc[2*q+1]);
    uint4* op = (uint4*)(g_h2h + (size_t)nid * D2);
#pragma unroll
    for (int q = 0; q < 5; q++) op[q] = ((uint4*)hp)[q];
    g_el2h[nid] = __float2half(ela);
    g_er2 [nid] = era;
}

// ---------------- K5: layer2 CSR agg + fused bias + log_softmax (warp per dst) ----------------
__global__ __launch_bounds__(256) void k_agg2(const float* __restrict__ b2,
                                              float* __restrict__ out, int n) {
    int d = blockIdx.x * 8 + (threadIdx.x >> 5);
    int lane = threadIdx.x & 31;

    if (lane == 0 && d < n) g_hist[d] = 0;
    if (d == 0 && lane == 0) g_counter = 0;

    if (d >= n) return;
    int j = lane % 10;
    int g = lane / 10;       // 0,1,2 (lanes 30,31: g==3 -> idle)

    float er = g_er2[d];
    int k0 = g_rowstart[d], k1 = g_cursor[d];
    if (g >= 3) { k0 = 0; k1 = 0; }

    float acc[4] = {0.f, 0.f, 0.f, 0.f};
    float denom = 0.f;
    for (int k = k0 + g; k < k1; k += 3) {
        int s = __ldg(g_sorted + k);
        float el = __half2float(__ldg(g_el2h + s));
        uint2 hv = __ldg((const uint2*)(g_h2h + (size_t)s * D2 + j * 4));
        float ex = __expf(lrelu(el + er));
        const __half2* hp = (const __half2*)&hv;
        float2 f0 = __half22float2(hp[0]);
        float2 f1 = __half22float2(hp[1]);
        acc[0] = fmaf(ex, f0.x, acc[0]);
        acc[1] = fmaf(ex, f0.y, acc[1]);
        acc[2] = fmaf(ex, f1.x, acc[2]);
        acc[3] = fmaf(ex, f1.y, acc[3]);
        denom += ex;
    }
    __syncwarp();
#pragma unroll
    for (int q = 0; q < 4; q++) {
        float a = __shfl_down_sync(0xffffffffu, acc[q], 10);
        float b = __shfl_down_sync(0xffffffffu, acc[q], 20);
        acc[q] += a + b;
    }
    {
        float a = __shfl_down_sync(0xffffffffu, denom, 10);
        float b = __shfl_down_sync(0xffffffffu, denom, 20);
        denom += a + b;
    }

    float v[4];
    float m = -1e30f;
    float iv = denom > 0.f ? __fdividef(1.f, denom) : 0.f;
    if (lane < 10) {
#pragma unroll
        for (int q = 0; q < 4; q++) {
            v[q] = acc[q] * iv + __ldg(b2 + j * 4 + q);
            m = fmaxf(m, v[q]);
        }
    }
#pragma unroll
    for (int off = 1; off < 16; off <<= 1)
        m = fmaxf(m, __shfl_xor_sync(0xffffffffu, m, off));
    float s = 0.f;
    if (lane < 10) {
#pragma unroll
        for (int q = 0; q < 4; q++) s += __expf(v[q] - m);
    }
#pragma unroll
    for (int off = 1; off < 16; off <<= 1)
        s += __shfl_xor_sync(0xffffffffu, s, off);

    if (lane < 10) {
        float lse = m + logf(s);
        *(float4*)(out + (size_t)d * D2 + j * 4) =
            make_float4(v[0] - lse, v[1] - lse, v[2] - lse, v[3] - lse);
    }
}

// ---------------- launch ----------------
extern "C" void kernel_launch(void* const* d_in, const int* in_sizes, int n_in,
                              void* d_out, int out_size) {
    const float* x   = (const float*)d_in[0];
    const int*   src = (const int*)d_in[1];
    const int*   dst = (const int*)d_in[2];
    const float* W1  = (const float*)d_in[3];
    const float* al1 = (const float*)d_in[4];
    const float* ar1 = (const float*)d_in[5];
    const float* b1  = (const float*)d_in[6];
    const float* W2  = (const float*)d_in[7];
    const float* al2 = (const float*)d_in[8];
    const float* ar2 = (const float*)d_in[9];
    const float* b2  = (const float*)d_in[10];

    int n = in_sizes[0] / INF;
    int e = in_sizes[1];

    int nb_node = (n + 255) / 256;
    int nb_edge = (e + 255) / 256;
    int nb_gemm = (n + 127) / 128;
    int nb_warp = (n + 7) / 8;          // warp-per-dst kernels

    static cudaStream_t s_side = nullptr;
    static cudaEvent_t  s_evA  = nullptr;
    static cudaEvent_t  s_evB  = nullptr;
    if (s_side == nullptr) {
        cudaStreamCreateWithFlags(&s_side, cudaStreamNonBlocking);
        cudaEventCreateWithFlags(&s_evA, cudaEventDisableTiming);
        cudaEventCreateWithFlags(&s_evB, cudaEventDisableTiming);
    }

    // fork: CSR build on side stream, GEMM1 on main stream
    cudaEventRecord(s_evA, 0);
    cudaStreamWaitEvent(s_side, s_evA, 0);

    k_hist    <<<nb_edge, 256, 0, s_side>>>(dst, e);
    k_rowalloc<<<nb_node, 256, 0, s_side>>>(n);
    k_scatter <<<nb_edge, 256, 0, s_side>>>(src, dst, e);
    cudaEventRecord(s_evB, s_side);

    k_gemm1   <<<nb_gemm, 256>>>(x, W1, al1, ar1, n);   // 4th launch -> ncu profiles this

    // join
    cudaStreamWaitEvent(0, s_evB, 0);

    k_agg1    <<<nb_warp, 256>>>(n);
    k_node2   <<<nb_node, 256>>>(W2, al2, ar2, b1, n);
    k_agg2    <<<nb_warp, 256>>>(b2, (float*)d_out, n);
}

// round 17
// speedup vs baseline: 1.2109x; 1.0039x over previous
#include <cuda_runtime.h>
#include <cuda_fp16.h>

// ---------------- problem constants ----------------
#define NMAX 100000
#define EMAX 1600000
#define INF 512
#define D1 64      // H1*F1 = 8*8
#define H1N 8
#define D2 40      // H2*F2 = 1*40

// ---------------- device scratch ----------------
__device__ __align__(16) __half g_h1h [NMAX * D1];   // fp16 layer1 features (gather payload)
__device__ __align__(16) __half g_el1h[NMAX * H1N];  // fp16 src-side attention
__device__ __align__(16) float  g_er1 [NMAX * H1N];  // fp32 dst-side attention
__device__ __align__(16) float  g_agg1[NMAX * D1];   // normalized layer1 output (pre-bias)
__device__ __align__(16) __half g_h2h [NMAX * D2];   // fp16 layer2 features
__device__ __align__(16) __half g_el2h[NMAX];
__device__ __align__(16) float  g_er2 [NMAX];
// CSR scratch (zeroed at module load; k_agg2 re-zeroes hist/counter each call)
__device__ int g_hist[NMAX];
__device__ int g_rowstart[NMAX];
__device__ int g_cursor[NMAX];
__device__ int g_sorted[EMAX];
__device__ int g_counter;

// ---------------- helpers ----------------
__device__ __forceinline__ float lrelu(float v) { return v >= 0.f ? v : 0.2f * v; }
__device__ __forceinline__ float eluf(float v)  { return v > 0.f ? v : expm1f(v); }

__device__ __forceinline__ void mma_f16(float* c,
                                        unsigned a0, unsigned a1, unsigned a2, unsigned a3,
                                        unsigned b0, unsigned b1) {
    asm volatile(
        "mma.sync.aligned.m16n8k16.row.col.f32.f16.f16.f32 "
        "{%0,%1,%2,%3},{%4,%5,%6,%7},{%8,%9},{%0,%1,%2,%3};"
        : "+f"(c[0]), "+f"(c[1]), "+f"(c[2]), "+f"(c[3])
        : "r"(a0), "r"(a1), "r"(a2), "r"(a3), "r"(b0), "r"(b1));
}
// L2-only (bypass L1) 16B async copy — streaming data with zero reuse.
__device__ __forceinline__ void cpa16cg(unsigned sa, const void* g, int sz) {
    asm volatile("cp.async.cg.shared.global [%0], [%1], 16, %2;"
                 :: "r"(sa), "l"(g), "r"(sz));
}
__device__ __forceinline__ void cpa_commit() { asm volatile("cp.async.commit_group;"); }
__device__ __forceinline__ void cpa_wait1()  { asm volatile("cp.async.wait_group 1;"); }
__device__ __forceinline__ void cpa_wait0()  { asm volatile("cp.async.wait_group 0;"); }
__device__ __forceinline__ unsigned h2u(__half2 h) {
    unsigned u; asm("mov.b32 %0, %1;" : "=r"(u) : "r"(*(unsigned*)&h)); return u;
}

// ---------------- K_hist (g_hist arrives zeroed) ----------------
__global__ __launch_bounds__(256) void k_hist(const int* __restrict__ dst, int e) {
    int i = blockIdx.x * 256 + threadIdx.x;
    if (i < e) atomicAdd(&g_hist[dst[i]], 1);
}

// ---------------- K_rowalloc: warp-scanned row offsets ----------------
__global__ __launch_bounds__(256) void k_rowalloc(int n) {
    int d = blockIdx.x * 256 + threadIdx.x;
    int lane = threadIdx.x & 31;
    int c = (d < n) ? g_hist[d] : 0;
    int sum = c;
#pragma unroll
    for (int off = 1; off < 32; off <<= 1) {
        int v = __shfl_up_sync(0xffffffffu, sum, off);
        if (lane >= off) sum += v;
    }
    int total = __shfl_sync(0xffffffffu, sum, 31);
    int base = 0;
    if (lane == 31) base = atomicAdd(&g_counter, total);
    base = __shfl_sync(0xffffffffu, base, 31);
    if (d < n) {
        int st = base + sum - c;
        g_rowstart[d] = st;
        g_cursor[d]   = st;
    }
}

// ---------------- K_scatter ----------------
__global__ __launch_bounds__(256) void k_scatter(const int* __restrict__ src,
                                                 const int* __restrict__ dst, int e) {
    int i = blockIdx.x * 256 + threadIdx.x;
    if (i >= e) return;
    int p = atomicAdd(&g_cursor[dst[i]], 1);
    g_sorted[p] = src[i];
}

// ---------------- K1: h1 = x @ W1, fp16 mma m16n8k16, 3-stage cp.async.cg ring for x ----------------
// Dynamic smem (floats): xs 3 stages x [128][36] fp32 (0..13824),
//                        ws fp16 2 stages x 2304 halves (13824..16128), al/ar (16128..16256).
// x copy for tile tt+1 is issued during tile tt-1 -> 2 compute-tiles of latency slack.
// W register-prefetch path identical to R16. ONE __syncthreads per tile.
// Epilogue ds[128][64] fp32 overlays xs stage 0-1.
__global__ __launch_bounds__(256) void k_gemm1(const float* __restrict__ x,
                                               const float* __restrict__ W1,
                                               const float* __restrict__ al1,
                                               const float* __restrict__ ar1, int n) {
    extern __shared__ __align__(16) float sm[];
    __half* ws_h = (__half*)(sm + 13824);
    unsigned* ws_u = (unsigned*)ws_h;
    float* alr = sm + 16128;

    const int tx = threadIdx.x;
    const int row0 = blockIdx.x * 128;
    const int warp = tx >> 5;
    const int lane = tx & 31;
    const int g  = lane >> 2;
    const int tg = lane & 3;
    const int wrow = warp * 16;

    const unsigned xs_base = (unsigned)__cvta_generic_to_shared(sm);

    if (tx < 64) alr[tx] = al1[tx];
    else if (tx < 128) alr[tx] = ar1[tx - 64];

    // per-thread x-chunk coordinates (4 chunks of 16B per tile)
    int crow[4], ccol[4];
#pragma unroll
    for (int it = 0; it < 4; it++) {
        int slot = tx + it * 256;
        crow[it] = slot >> 3;        // row 0..127
        ccol[it] = slot & 7;         // 16B chunk 0..7 within 32-float row
    }

    // issue x copies for one tile into stage tt%3, one commit group per tile
    auto issue_x = [&](int tt) {
        int stage = tt % 3;
#pragma unroll
        for (int it = 0; it < 4; it++) {
            int grow = row0 + crow[it];
            unsigned sa = xs_base + (unsigned)((stage * 4608 + crow[it] * 36 + ccol[it] * 4) * 4);
            cpa16cg(sa, x + (size_t)grow * INF + tt * 32 + ccol[it] * 4, grow < n ? 16 : 0);
        }
        cpa_commit();
    };

    float4 wr[2];

    // ---- prologue: x tiles 0,1 in flight; W tile 0 in smem ----
    issue_x(0);
    issue_x(1);
#pragma unroll
    for (int it = 0; it < 2; it++) {
        int slot = tx + it * 256;
        int k = slot >> 4;
        int n4 = (slot & 15) << 2;
        wr[it] = *(const float4*)(W1 + (size_t)k * D1 + n4);
    }
#pragma unroll
    for (int it = 0; it < 2; it++) {
        int slot = tx + it * 256;
        int k = slot >> 4;
        int n4 = (slot & 15) << 2;
        int base = (k >> 1) * 144 + (k & 1);
        ws_h[base + (n4 + 0) * 2] = __float2half(wr[it].x);
        ws_h[base + (n4 + 1) * 2] = __float2half(wr[it].y);
        ws_h[base + (n4 + 2) * 2] = __float2half(wr[it].z);
        ws_h[base + (n4 + 3) * 2] = __float2half(wr[it].w);
    }
    cpa_wait1();            // x tile 0 complete (tile 1 may still be in flight)
    __syncthreads();

    float acc[8][4];
#pragma unroll
    for (int j = 0; j < 8; j++)
#pragma unroll
        for (int q = 0; q < 4; q++) acc[j][q] = 0.f;

    for (int tt = 0; tt < 16; tt++) {
        // issue x copies for tile tt+2 and W loads for tile tt+1 (overlap compute)
        if (tt < 14) issue_x(tt + 2);
        if (tt < 15) {
            int k0 = (tt + 1) * 32;
#pragma unroll
            for (int it = 0; it < 2; it++) {
                int slot = tx + it * 256;
                int k = slot >> 4;
                int n4 = (slot & 15) << 2;
                wr[it] = *(const float4*)(W1 + (size_t)(k0 + k) * D1 + n4);
            }
        }

        // compute tile tt: 2 k16 steps, A frags from fp32 smem (cvt at load)
        const float* xc = sm + (tt % 3) * 4608;
        const unsigned* wsb = ws_u + (tt & 1) * 1152;
#pragma unroll
        for (int ks = 0; ks < 2; ks++) {
            int base = (wrow + g) * 36 + ks * 16 + 2 * tg;
            float2 fa0 = *(const float2*)(xc + base);
            float2 fa1 = *(const float2*)(xc + base + 8 * 36);
            float2 fa2 = *(const float2*)(xc + base + 8);
            float2 fa3 = *(const float2*)(xc + base + 8 * 36 + 8);
            unsigned a0 = h2u(__floats2half2_rn(fa0.x, fa0.y));
            unsigned a1 = h2u(__floats2half2_rn(fa1.x, fa1.y));
            unsigned a2 = h2u(__floats2half2_rn(fa2.x, fa2.y));
            unsigned a3 = h2u(__floats2half2_rn(fa3.x, fa3.y));
            const unsigned* bp0 = wsb + (ks * 8 + tg) * 72 + g;
            const unsigned* bp1 = bp0 + 4 * 72;
#pragma unroll
            for (int j = 0; j < 8; j++)
                mma_f16(acc[j], a0, a1, a2, a3, bp0[8 * j], bp1[8 * j]);
        }

        if (tt < 15) {
            // store W tile tt+1 into the other W buffer (read of that buffer ended at tt-1's barrier)
            int nxt = (tt + 1) & 1;
#pragma unroll
            for (int it = 0; it < 2; it++) {
                int slot = tx + it * 256;
                int k = slot >> 4;
                int n4 = (slot & 15) << 2;
                int base = nxt * 2304 + (k >> 1) * 144 + (k & 1);
                ws_h[base + (n4 + 0) * 2] = __float2half(wr[it].x);
                ws_h[base + (n4 + 1) * 2] = __float2half(wr[it].y);
                ws_h[base + (n4 + 2) * 2] = __float2half(wr[it].z);
                ws_h[base + (n4 + 3) * 2] = __float2half(wr[it].w);
            }
            // x tile tt+1 must be complete; pending groups: tt+2 only -> wait_group 1
            if (tt < 14) cpa_wait1(); else cpa_wait0();
            __syncthreads();
        }
    }
    __syncthreads();   // all warps done reading xs before ds overlay

    // ---- epilogue: accumulators -> smem ds[128][64] fp32 ----
    float* ds = sm;
#pragma unroll
    for (int j = 0; j < 8; j++) {
        *(float2*)&ds[(wrow + g) * 64 + 8 * j + 2 * tg]     = make_float2(acc[j][0], acc[j][1]);
        *(float2*)&ds[(wrow + g + 8) * 64 + 8 * j + 2 * tg] = make_float2(acc[j][2], acc[j][3]);
    }
    __syncthreads();

    // thread tx: row = tx>>1, half ch = tx&1 -> cols ch*32..+31 (heads 4ch..4ch+3)
    {
        int row = tx >> 1;
        int ch = tx & 1;
        int grow = row0 + row;
        if (grow < n) {
            const float* dp  = ds + row * 64 + ch * 32;
            const float* alp = alr + ch * 32;
            const float* arp = alr + 64 + ch * 32;
            float h[32];
#pragma unroll
            for (int q = 0; q < 8; q++) *(float4*)&h[q * 4] = *(const float4*)(dp + q * 4);

            float elv[4], erv[4];
#pragma unroll
            for (int q = 0; q < 4; q++) {
                float el = 0.f, er = 0.f;
#pragma unroll
                for (int c = 0; c < 8; c++) {
                    el = fmaf(h[q * 8 + c], alp[q * 8 + c], el);
                    er = fmaf(h[q * 8 + c], arp[q * 8 + c], er);
                }
                elv[q] = el; erv[q] = er;
            }
            __half2 ph[16];
#pragma unroll
            for (int q = 0; q < 16; q++) ph[q] = __floats2half2_rn(h[2 * q], h[2 * q + 1]);
            uint4* hop = (uint4*)(g_h1h + (size_t)grow * D1 + ch * 32);
#pragma unroll
            for (int q = 0; q < 4; q++) hop[q] = ((uint4*)ph)[q];

            __half e4[4];
#pragma unroll
            for (int q = 0; q < 4; q++) e4[q] = __float2half(elv[q]);
            *(uint2*)(g_el1h + (size_t)grow * 8 + ch * 4) = *(uint2*)e4;
            *(float4*)(g_er1 + (size_t)grow * 8 + ch * 4) =
                make_float4(erv[0], erv[1], erv[2], erv[3]);
        }
    }
}

// ---------------- K3: layer1 CSR aggregation (warp per dst, 8 slots x 4 edge groups) ----------------
__global__ __launch_bounds__(256) void k_agg1(int n) {
    int d = blockIdx.x * 8 + (threadIdx.x >> 5);
    if (d >= n) return;
    int lane = threadIdx.x & 31;
    int j = lane & 7;        // slot / head 0..7
    int g = lane >> 3;       // edge group 0..3

    float er = g_er1[(size_t)d * 8 + j];
    int k0 = g_rowstart[d], k1 = g_cursor[d];

    float acc[8] = {0.f, 0.f, 0.f, 0.f, 0.f, 0.f, 0.f, 0.f};
    float denom = 0.f;
    for (int k = k0 + g; k < k1; k += 4) {
        int s = __ldg(g_sorted + k);
        float el = __half2float(__ldg(g_el1h + (size_t)s * 8 + j));
        uint4 hv = __ldg((const uint4*)(g_h1h + (size_t)s * D1 + j * 8));
        float ex = __expf(lrelu(el + er));
        const __half2* hp = (const __half2*)&hv;
#pragma unroll
        for (int q = 0; q < 4; q++) {
            float2 f = __half22float2(hp[q]);
            acc[2*q]   = fmaf(ex, f.x, acc[2*q]);
            acc[2*q+1] = fmaf(ex, f.y, acc[2*q+1]);
        }
        denom += ex;
    }
    __syncwarp();
#pragma unroll
    for (int q = 0; q < 8; q++) {
        acc[q] += __shfl_down_sync(0xffffffffu, acc[q], 16);
        acc[q] += __shfl_down_sync(0xffffffffu, acc[q], 8);
    }
    denom += __shfl_down_sync(0xffffffffu, denom, 16);
    denom += __shfl_down_sync(0xffffffffu, denom, 8);

    if (g == 0) {
        float iv = denom > 0.f ? __fdividef(1.f, denom) : 0.f;
        float* op = g_agg1 + (size_t)d * D1 + j * 8;
        *(float4*)(op)     = make_float4(acc[0]*iv, acc[1]*iv, acc[2]*iv, acc[3]*iv);
        *(float4*)(op + 4) = make_float4(acc[4]*iv, acc[5]*iv, acc[6]*iv, acc[7]*iv);
    }
}

// ---------------- K4: node: ELU(agg1 + b1), GEMM2 (64->40) vectorized, el2/er2, fp16 h2 ----------------
__global__ __launch_bounds__(256) void k_node2(const float* __restrict__ W2,
                                               const float* __restrict__ al2,
                                               const float* __restrict__ ar2,
                                               const float* __restrict__ b1, int n) {
    __shared__ __align__(16) float w2s[64 * 40];
    __shared__ float sal[40], sar[40], sb1[64];
    for (int i = threadIdx.x; i < 64 * 40; i += 256) w2s[i] = W2[i];
    if (threadIdx.x < 40) { sal[threadIdx.x] = al2[threadIdx.x]; sar[threadIdx.x] = ar2[threadIdx.x]; }
    if (threadIdx.x < 64) sb1[threadIdx.x] = b1[threadIdx.x];
    __syncthreads();
    int nid = blockIdx.x * 256 + threadIdx.x;
    if (nid >= n) return;

    float acc[40];
#pragma unroll
    for (int c = 0; c < 40; c++) acc[c] = 0.f;

    const float4* ap = (const float4*)(g_agg1 + (size_t)nid * D1);
    for (int j = 0; j < 16; j++) {
        float4 tv = ap[j];
        const float* bp = sb1 + j * 4;
        float v0 = eluf(tv.x + bp[0]);
        float v1 = eluf(tv.y + bp[1]);
        float v2 = eluf(tv.z + bp[2]);
        float v3 = eluf(tv.w + bp[3]);
        const float4* w0 = (const float4*)&w2s[(j * 4 + 0) * 40];
        const float4* w1 = (const float4*)&w2s[(j * 4 + 1) * 40];
        const float4* w2 = (const float4*)&w2s[(j * 4 + 2) * 40];
        const float4* w3 = (const float4*)&w2s[(j * 4 + 3) * 40];
#pragma unroll
        for (int q = 0; q < 10; q++) {
            float4 a = w0[q], b = w1[q], c = w2[q], d = w3[q];
            acc[q*4+0] = fmaf(v0, a.x, fmaf(v1, b.x, fmaf(v2, c.x, fmaf(v3, d.x, acc[q*4+0]))));
            acc[q*4+1] = fmaf(v0, a.y, fmaf(v1, b.y, fmaf(v2, c.y, fmaf(v3, d.y, acc[q*4+1]))));
            acc[q*4+2] = fmaf(v0, a.z, fmaf(v1, b.z, fmaf(v2, c.z, fmaf(v3, d.z, acc[q*4+2]))));
            acc[q*4+3] = fmaf(v0, a.w, fmaf(v1, b.w, fmaf(v2, c.w, fmaf(v3, d.w, acc[q*4+3]))));
        }
    }

    float ela = 0.f, era = 0.f;
#pragma unroll
    for (int c = 0; c < 40; c++) {
        ela = fmaf(acc[c], sal[c], ela);
        era = fmaf(acc[c], sar[c], era);
    }
    __half2 hp[20];
#pragma unroll
    for (int q = 0; q < 20; q++) hp[q] = __floats2half2_rn(acc[2*q], acc[2*q+1]);
    uint4* op = (uint4*)(g_h2h + (size_t)nid * D2);
#pragma unroll
    for (int q = 0; q < 5; q++) op[q] = ((uint4*)hp)[q];
    g_el2h[nid] = __float2half(ela);
    g_er2 [nid] = era;
}

// ---------------- K5: layer2 CSR agg + fused bias + log_softmax (warp per dst) ----------------
__global__ __launch_bounds__(256) void k_agg2(const float* __restrict__ b2,
                                              float* __restrict__ out, int n) {
    int d = blockIdx.x * 8 + (threadIdx.x >> 5);
    int lane = threadIdx.x & 31;

    if (lane == 0 && d < n) g_hist[d] = 0;
    if (d == 0 && lane == 0) g_counter = 0;

    if (d >= n) return;
    int j = lane % 10;
    int g = lane / 10;       // 0,1,2 (lanes 30,31: g==3 -> idle)

    float er = g_er2[d];
    int k0 = g_rowstart[d], k1 = g_cursor[d];
    if (g >= 3) { k0 = 0; k1 = 0; }

    float acc[4] = {0.f, 0.f, 0.f, 0.f};
    float denom = 0.f;
    for (int k = k0 + g; k < k1; k += 3) {
        int s = __ldg(g_sorted + k);
        float el = __half2float(__ldg(g_el2h + s));
        uint2 hv = __ldg((const uint2*)(g_h2h + (size_t)s * D2 + j * 4));
        float ex = __expf(lrelu(el + er));
        const __half2* hp = (const __half2*)&hv;
        float2 f0 = __half22float2(hp[0]);
        float2 f1 = __half22float2(hp[1]);
        acc[0] = fmaf(ex, f0.x, acc[0]);
        acc[1] = fmaf(ex, f0.y, acc[1]);
        acc[2] = fmaf(ex, f1.x, acc[2]);
        acc[3] = fmaf(ex, f1.y, acc[3]);
        denom += ex;
    }
    __syncwarp();
#pragma unroll
    for (int q = 0; q < 4; q++) {
        float a = __shfl_down_sync(0xffffffffu, acc[q], 10);
        float b = __shfl_down_sync(0xffffffffu, acc[q], 20);
        acc[q] += a + b;
    }
    {
        float a = __shfl_down_sync(0xffffffffu, denom, 10);
        float b = __shfl_down_sync(0xffffffffu, denom, 20);
        denom += a + b;
    }

    float v[4];
    float m = -1e30f;
    float iv = denom > 0.f ? __fdividef(1.f, denom) : 0.f;
    if (lane < 10) {
#pragma unroll
        for (int q = 0; q < 4; q++) {
            v[q] = acc[q] * iv + __ldg(b2 + j * 4 + q);
            m = fmaxf(m, v[q]);
        }
    }
#pragma unroll
    for (int off = 1; off < 16; off <<= 1)
        m = fmaxf(m, __shfl_xor_sync(0xffffffffu, m, off));
    float s = 0.f;
    if (lane < 10) {
#pragma unroll
        for (int q = 0; q < 4; q++) s += __expf(v[q] - m);
    }
#pragma unroll
    for (int off = 1; off < 16; off <<= 1)
        s += __shfl_xor_sync(0xffffffffu, s, off);

    if (lane < 10) {
        float lse = m + logf(s);
        *(float4*)(out + (size_t)d * D2 + j * 4) =
            make_float4(v[0] - lse, v[1] - lse, v[2] - lse, v[3] - lse);
    }
}

// ---------------- launch ----------------
extern "C" void kernel_launch(void* const* d_in, const int* in_sizes, int n_in,
                              void* d_out, int out_size) {
    const float* x   = (const float*)d_in[0];
    const int*   src = (const int*)d_in[1];
    const int*   dst = (const int*)d_in[2];
    const float* W1  = (const float*)d_in[3];
    const float* al1 = (const float*)d_in[4];
    const float* ar1 = (const float*)d_in[5];
    const float* b1  = (const float*)d_in[6];
    const float* W2  = (const float*)d_in[7];
    const float* al2 = (const float*)d_in[8];
    const float* ar2 = (const float*)d_in[9];
    const float* b2  = (const float*)d_in[10];

    int n = in_sizes[0] / INF;
    int e = in_sizes[1];

    const int GEMM_SMEM = 16256 * 4;   // 65,024 B dynamic smem

    int nb_node = (n + 255) / 256;
    int nb_edge = (e + 255) / 256;
    int nb_gemm = (n + 127) / 128;
    int nb_warp = (n + 7) / 8;          // warp-per-dst kernels

    static cudaStream_t s_side = nullptr;
    static cudaEvent_t  s_evA  = nullptr;
    static cudaEvent_t  s_evB  = nullptr;
    if (s_side == nullptr) {
        cudaStreamCreateWithFlags(&s_side, cudaStreamNonBlocking);
        cudaEventCreateWithFlags(&s_evA, cudaEventDisableTiming);
        cudaEventCreateWithFlags(&s_evB, cudaEventDisableTiming);
        cudaFuncSetAttribute(k_gemm1, cudaFuncAttributeMaxDynamicSharedMemorySize, GEMM_SMEM);
    }

    // fork: CSR build on side stream, GEMM1 on main stream
    cudaEventRecord(s_evA, 0);
    cudaStreamWaitEvent(s_side, s_evA, 0);

    k_hist    <<<nb_edge, 256, 0, s_side>>>(dst, e);
    k_rowalloc<<<nb_node, 256, 0, s_side>>>(n);
    k_scatter <<<nb_edge, 256, 0, s_side>>>(src, dst, e);
    cudaEventRecord(s_evB, s_side);

    k_gemm1   <<<nb_gemm, 256, GEMM_SMEM>>>(x, W1, al1, ar1, n);  // profiled launch

    // join
    cudaStreamWaitEvent(0, s_evB, 0);

    k_agg1    <<<nb_warp, 256>>>(n);
    k_node2   <<<nb_node, 256>>>(W2, al2, ar2, b1, n);
    k_agg2    <<<nb_warp, 256>>>(b2, (float*)d_out, n);
}